// round 11
// baseline (speedup 1.0000x reference)
#include <cuda_runtime.h>
#include <cstdint>

// Paillier 2x2 "sum" pooling = windowed modular product of ciphertexts mod n^2.
// n = 46337, NSQ = n^2 = 2147117569 < 2^31. Input int32, output float32.
//
// Montgomery multiplication with R = 2^32, lazy residues in [0, 2N):
//   mm(mm(mm(mm(a,b),c),d), R^4 mod N) == a*b*c*d mod N  (one final fixup)
//
// History: R8 dense 4ch/thread: 94.5us, DRAM 84.6%, L1 23.7%.
//          R9 8ch/thread stride-2: 96.6us REGRESS (L1 46% — broken coalescing).
//          R10 R8+.CS: 94.1us, neutral.
// R11: dense layout preserved, but 2 independent far-apart units per thread
//      -> 8 front-batched dense LDG.128 (MLP_p1 8) to push DRAM active higher.

static constexpr uint32_t NSQ = 2147117569u;  // 46337^2

static constexpr uint32_t compute_np() {
    uint32_t inv = NSQ;
    for (int i = 0; i < 5; ++i) inv *= (2u - NSQ * inv);
    return (uint32_t)(0u - inv);
}
static constexpr uint32_t NPRIME = compute_np();

static constexpr uint32_t compute_r4() {
    uint64_t r = 1;
    for (int i = 0; i < 128; ++i) r = (r * 2u) % (uint64_t)NSQ;
    return (uint32_t)r;
}
static constexpr uint32_t R4 = compute_r4();

__device__ __forceinline__ uint32_t montmul(uint32_t a, uint32_t b) {
    uint64_t t = (uint64_t)a * (uint64_t)b;         // IMAD.WIDE
    uint32_t m = (uint32_t)t * NPRIME;              // IMAD (lo32)
    uint64_t u = t + (uint64_t)m * (uint64_t)NSQ;   // IMAD.WIDE (64-bit acc)
    return (uint32_t)(u >> 32);
}

__device__ __forceinline__ float pool4(uint32_t a, uint32_t b,
                                       uint32_t c, uint32_t d) {
    uint32_t x = montmul(a, b);   // < 2N
    x = montmul(x, c);            // < 2N
    x = montmul(x, d);            // < 2N
    x = montmul(x, R4);           // abcd mod' N, < 2N
    uint32_t y = x - NSQ;
    x = min(x, y);                // branchless final reduce
    return (float)x;
}

__device__ __forceinline__ float4 pool4x4(uint4 a, uint4 b, uint4 c, uint4 d) {
    float4 r;
    r.x = pool4(a.x, b.x, c.x, d.x);
    r.y = pool4(a.y, b.y, c.y, d.y);
    r.z = pool4(a.z, b.z, c.z, d.z);
    r.w = pool4(a.w, b.w, c.w, d.w);
    return r;
}

// Shapes: B=32, H=256, W=256, C=64 -> Ho=Wo=128. int32 in, float32 out.
// 4,194,304 threads; each handles unit t and unit t + 4,194,304 (far half).
// Per unit: 4 dense LDG.128 + 1 STG.128, identical mapping to R8/R10.
__global__ __launch_bounds__(256)
void paillier_pool_kernel(const uint4* __restrict__ in,
                          float4* __restrict__ out) {
    uint32_t tid = blockIdx.x * 256u + threadIdx.x;

    // ---- unit 0: tid in [0, 4M) -> hob in [0, 2048) (first 16 batches) ----
    uint32_t c4  = tid & 15u;
    uint32_t wo  = (tid >> 4) & 127u;
    uint32_t hob = tid >> 11;                 // [0, 2048)

    // ---- unit 1: same (c4, wo), hob + 2048 (second half of batches) ----
    uint32_t base0 = hob * 8192u + wo * 32u + c4;
    uint32_t base1 = base0 + 2048u * 8192u;   // + 16,777,216 uint4

    const uint4* p0 = in + base0;
    const uint4* p1 = in + base1;

    // 8 front-batched dense streaming loads (each warp LDG: 2x256B segments).
    uint4 a00 = __ldcs(p0);            uint4 a01 = __ldcs(p0 + 16u);
    uint4 a10 = __ldcs(p0 + 4096u);    uint4 a11 = __ldcs(p0 + 4112u);
    uint4 b00 = __ldcs(p1);            uint4 b01 = __ldcs(p1 + 16u);
    uint4 b10 = __ldcs(p1 + 4096u);    uint4 b11 = __ldcs(p1 + 4112u);

    float4 r0 = pool4x4(a00, a01, a10, a11);
    float4 r1 = pool4x4(b00, b01, b10, b11);

    uint32_t obase0 = hob * 2048u + wo * 16u + c4;
    __stcs(out + obase0, r0);
    __stcs(out + obase0 + 2048u * 2048u, r1);   // hob+2048 half
}

extern "C" void kernel_launch(void* const* d_in, const int* in_sizes, int n_in,
                              void* d_out, int out_size) {
    (void)in_sizes; (void)n_in; (void)out_size;
    const uint4* in = (const uint4*)d_in[0];
    float4* out = (float4*)d_out;
    // 4,194,304 threads / 256 = 16384 blocks
    paillier_pool_kernel<<<16384, 256>>>(in, out);
}

// round 12
// speedup vs baseline: 1.0020x; 1.0020x over previous
#include <cuda_runtime.h>
#include <cstdint>

// Paillier 2x2 "sum" pooling = windowed modular product of ciphertexts mod n^2.
// n = 46337, NSQ = n^2 = 2147117569 < 2^31. Input int32, output float32.
//
// Montgomery multiplication with R = 2^32, lazy residues in [0, 2N):
//   mm(mm(mm(mm(a,b),c),d), R^4 mod N) == a*b*c*d mod N  (one final fixup)
//
// Evidence trail:
//   R8  dense 4ch/thread:        94.5us, DRAM 84.6%, L1 23.7%
//   R9  8ch stride-2:            96.6us REGRESS (L1 46%: broken coalescing)
//   R10 R8 + .CS hints:          94.1us (best)
//   R11 2 far units (MLP_p1 8):  95.0us neutral -> DRAM path saturated
// R12 = R10 with 512-thread blocks (fewer CTA boundaries, larger contiguous
//       per-CTA footprint). Kernel is HBM-streaming bound at ~85% of spec;
//       traffic (512 MiB + 128 MiB, single-touch) is minimal.

static constexpr uint32_t NSQ = 2147117569u;  // 46337^2

static constexpr uint32_t compute_np() {
    uint32_t inv = NSQ;
    for (int i = 0; i < 5; ++i) inv *= (2u - NSQ * inv);
    return (uint32_t)(0u - inv);
}
static constexpr uint32_t NPRIME = compute_np();

static constexpr uint32_t compute_r4() {
    uint64_t r = 1;
    for (int i = 0; i < 128; ++i) r = (r * 2u) % (uint64_t)NSQ;
    return (uint32_t)r;
}
static constexpr uint32_t R4 = compute_r4();

__device__ __forceinline__ uint32_t montmul(uint32_t a, uint32_t b) {
    uint64_t t = (uint64_t)a * (uint64_t)b;         // IMAD.WIDE
    uint32_t m = (uint32_t)t * NPRIME;              // IMAD (lo32)
    uint64_t u = t + (uint64_t)m * (uint64_t)NSQ;   // IMAD.WIDE (64-bit acc)
    return (uint32_t)(u >> 32);
}

__device__ __forceinline__ float pool4(uint32_t a, uint32_t b,
                                       uint32_t c, uint32_t d) {
    uint32_t x = montmul(a, b);   // < 2N
    x = montmul(x, c);            // < 2N
    x = montmul(x, d);            // < 2N
    x = montmul(x, R4);           // abcd mod' N, < 2N
    uint32_t y = x - NSQ;
    x = min(x, y);                // branchless final reduce
    return (float)x;
}

// Shapes: B=32, H=256, W=256, C=64 -> Ho=Wo=128. int32 in, float32 out.
// Each thread produces 4 adjacent channels (uint4 in, float4 out); warp access
// is per-instruction dense (threads 0-15 cover 256B contiguous per LDG).
// Threads = 32*128*128*16 = 8,388,608.
__global__ __launch_bounds__(512)
void paillier_pool_kernel(const uint4* __restrict__ in,
                          float4* __restrict__ out) {
    uint32_t tid = blockIdx.x * 512u + threadIdx.x;

    uint32_t c4  = tid & 15u;          // channel group  [0,16)
    uint32_t wo  = (tid >> 4) & 127u;  // output col     [0,128)
    uint32_t hob = tid >> 11;          // b*128 + ho     [0,4096)

    // Input elem idx (b, 2ho, 2wo, 4c4) = hob*32768 + wo*128 + 4c4.
    // uint4 units: base = hob*8192 + wo*32 + c4. Row stride (h+1) = 4096 uint4.
    uint32_t base = hob * 8192u + wo * 32u + c4;
    const uint4* p = in + base;

    // Front-batched streaming loads (4x LDG.E.128, evict-first).
    uint4 v00 = __ldcs(p);            // (h=2ho,   w=2wo)
    uint4 v01 = __ldcs(p + 16u);      // (h=2ho,   w=2wo+1)
    uint4 v10 = __ldcs(p + 4096u);    // (h=2ho+1, w=2wo)
    uint4 v11 = __ldcs(p + 4112u);    // (h=2ho+1, w=2wo+1)

    float4 r;
    r.x = pool4(v00.x, v01.x, v10.x, v11.x);
    r.y = pool4(v00.y, v01.y, v10.y, v11.y);
    r.z = pool4(v00.z, v01.z, v10.z, v11.z);
    r.w = pool4(v00.w, v01.w, v10.w, v11.w);

    // Output elem idx (b, ho, wo, 4c4): float4 units = hob*2048 + wo*16 + c4.
    __stcs(out + (hob * 2048u + wo * 16u + c4), r);
}

extern "C" void kernel_launch(void* const* d_in, const int* in_sizes, int n_in,
                              void* d_out, int out_size) {
    (void)in_sizes; (void)n_in; (void)out_size;
    const uint4* in = (const uint4*)d_in[0];
    float4* out = (float4*)d_out;
    // 8,388,608 threads / 512 = 16384 blocks
    paillier_pool_kernel<<<16384, 512>>>(in, out);
}